// round 4
// baseline (speedup 1.0000x reference)
#include <cuda_runtime.h>
#include <math.h>

#define BN    737280      // total elements (8 * 92160)
#define NPIX  92160       // elements per (b,t) slice
#define NTRK  512
#define NSEG  4096
#define NCH   66
#define CAP   320         // bucket capacity: mean 180, sigma 13.4 -> +10.4 sigma
#define MAXE  10          // CAP / 32
#define THR   2.0f
#define DKS   0.05f

// ---------------- scratch (device globals; no allocation) ----------------
__device__ int g_scnt[NSEG];
__device__ int g_order[NSEG * CAP];   // 5.24 MB

// ordered-uint mapping for floats (bijective, order-preserving)
__device__ __forceinline__ unsigned fok(float f) {
    unsigned b = __float_as_uint(f);
    return (b & 0x80000000u) ? ~b : (b | 0x80000000u);
}
__device__ __forceinline__ float kof(unsigned u) {
    unsigned b = (u & 0x80000000u) ? (u & 0x7FFFFFFFu) : ~u;
    return __uint_as_float(b);
}

// ---------------- kernels ----------------
__global__ void k_init() {
    int i = blockIdx.x * blockDim.x + threadIdx.x;
    if (i < NSEG) g_scnt[i] = 0;
}

// bucket valid elements by segment; copy invalid (gid<0) rows straight out
__global__ void __launch_bounds__(256)
k_bucket(const float* __restrict__ cen, const float* __restrict__ off,
         const float* __restrict__ opa, const float* __restrict__ sca,
         const float* __restrict__ rot, const float* __restrict__ fdc,
         const float* __restrict__ kp,  const float* __restrict__ ins,
         const float* __restrict__ mot, const int* __restrict__ gid,
         float* __restrict__ out) {
    int i = blockIdx.x * blockDim.x + threadIdx.x;
    if (i >= BN) return;
    int g = gid[i];
    if (g >= 0) {
        int s = (i / NPIX) * NTRK + g;
        int pos = atomicAdd(&g_scnt[s], 1);
        if (pos < CAP) g_order[s * CAP + pos] = i;
    } else {
        // rare (~0.2%): copy raw row
        float buf[NCH];
        #pragma unroll
        for (int c = 0; c < 3; c++) buf[c]      = cen[3 * i + c];
        #pragma unroll
        for (int c = 0; c < 3; c++) buf[3 + c]  = off[3 * i + c];
        buf[6] = opa[i];
        #pragma unroll
        for (int c = 0; c < 3; c++) buf[7 + c]  = sca[3 * i + c];
        float4 r4 = reinterpret_cast<const float4*>(rot)[i];
        buf[10] = r4.x; buf[11] = r4.y; buf[12] = r4.z; buf[13] = r4.w;
        #pragma unroll
        for (int c = 0; c < 3; c++) buf[14 + c] = fdc[3 * i + c];
        buf[17] = kp[i];
        const float4* ip = reinterpret_cast<const float4*>(ins) + (size_t)i * 8;
        #pragma unroll
        for (int q = 0; q < 8; q++) {
            float4 v = ip[q];
            buf[18 + 4 * q] = v.x; buf[19 + 4 * q] = v.y;
            buf[20 + 4 * q] = v.z; buf[21 + 4 * q] = v.w;
        }
        const float4* mp = reinterpret_cast<const float4*>(mot) + (size_t)i * 4;
        #pragma unroll
        for (int q = 0; q < 4; q++) {
            float4 v = mp[q];
            buf[50 + 4 * q] = v.x; buf[51 + 4 * q] = v.y;
            buf[52 + 4 * q] = v.z; buf[53 + 4 * q] = v.w;
        }
        float2* o2 = reinterpret_cast<float2*>(out + (size_t)i * NCH);
        #pragma unroll
        for (int c = 0; c < NCH / 2; c++)
            o2[c] = make_float2(buf[2 * c], buf[2 * c + 1]);
    }
}

// one warp per segment: phase-1 softmax mean, activity, phase-2 weighted
// merge, rep selection, and ALL row writes (merged or raw)
__global__ void __launch_bounds__(256)
k_mega(const float* __restrict__ cen, const float* __restrict__ off,
       const float* __restrict__ opa, const float* __restrict__ sca,
       const float* __restrict__ rot, const float* __restrict__ fdc,
       const float* __restrict__ kp,  const float* __restrict__ ins,
       const float* __restrict__ mot, float* __restrict__ out) {
    int s    = (blockIdx.x * blockDim.x + threadIdx.x) >> 5;   // segment id
    int lane = threadIdx.x & 31;
    if (s >= NSEG) return;
    int n = g_scnt[s];
    if (n > CAP) n = CAP;
    if (n == 0) return;       // warp-uniform

    const unsigned FULL = 0xFFFFFFFFu;
    int   idxv[MAXE];
    float kpv[MAXE];

    // ---- phase 1: z1, weighted center sums ----
    float z1 = 0.f, wx = 0.f, wy = 0.f, wz = 0.f;
    #pragma unroll
    for (int q = 0; q < MAXE; q++) {
        int p = lane + q * 32;
        bool v = p < n;
        int i = v ? g_order[s * CAP + p] : 0;
        idxv[q] = i;
        float k0 = v ? kp[i] : 0.f;
        kpv[q] = k0;
        if (v) {
            float e = __expf(k0);
            z1 += e;
            wx += e * cen[3 * i + 0];
            wy += e * cen[3 * i + 1];
            wz += e * cen[3 * i + 2];
        }
    }
    #pragma unroll
    for (int o = 16; o > 0; o >>= 1) {
        z1 += __shfl_xor_sync(FULL, z1, o);
        wx += __shfl_xor_sync(FULL, wx, o);
        wy += __shfl_xor_sync(FULL, wy, o);
        wz += __shfl_xor_sync(FULL, wz, o);
    }
    float zi1 = 1.f / fmaxf(z1, 1e-20f);
    float mx = wx * zi1, my = wy * zi1, mz = wz * zi1;

    // ---- activity + phase-2 z + representative key ----
    bool dupok = (n >= 2);
    unsigned amask = 0;
    float z2 = 0.f;
    unsigned long long key = ~0ull;
    #pragma unroll
    for (int q = 0; q < MAXE; q++) {
        int p = lane + q * 32;
        if (p < n && dupok) {
            int i = idxv[q];
            float dx = cen[3 * i + 0] - mx;
            float dy = cen[3 * i + 1] - my;
            float dz = cen[3 * i + 2] - mz;
            float d = sqrtf(dx * dx + dy * dy + dz * dz);
            if (d <= THR) {
                amask |= 1u << q;
                z2 += __expf(kpv[q]);
                unsigned long long k =
                    ((unsigned long long)(~fok(kpv[q])) << 32) | (unsigned)i;
                if (k < key) key = k;
            }
        }
    }
    #pragma unroll
    for (int o = 16; o > 0; o >>= 1) {
        z2 += __shfl_xor_sync(FULL, z2, o);
        unsigned long long ok = __shfl_xor_sync(FULL, key, o);
        if (ok < key) key = ok;
    }
    int   rep = (int)(unsigned)(key & 0xFFFFFFFFull);
    float m2  = kof(~(unsigned)(key >> 32));
    float zi2 = 1.f / fmaxf(z2, 1e-20f);

    // ================= chunk A: channels 0..17 =================
    {
        float acc[18];
        #pragma unroll
        for (int c = 0; c < 18; c++) acc[c] = 0.f;
        #pragma unroll
        for (int q = 0; q < MAXE; q++) {
            int p = lane + q * 32;
            if (p >= n) continue;
            int i = idxv[q];
            float t[18];
            #pragma unroll
            for (int c = 0; c < 3; c++) t[c]      = cen[3 * i + c];
            #pragma unroll
            for (int c = 0; c < 3; c++) t[3 + c]  = off[3 * i + c];
            t[6] = opa[i];
            #pragma unroll
            for (int c = 0; c < 3; c++) t[7 + c]  = sca[3 * i + c];
            float4 r4 = reinterpret_cast<const float4*>(rot)[i];
            t[10] = r4.x; t[11] = r4.y; t[12] = r4.z; t[13] = r4.w;
            #pragma unroll
            for (int c = 0; c < 3; c++) t[14 + c] = fdc[3 * i + c];
            t[17] = kpv[q];
            if ((amask >> q) & 1u) {
                float w = __expf(kpv[q]);
                #pragma unroll
                for (int c = 0; c < 18; c++) acc[c] += w * t[c];
            } else {
                float2* o2 = reinterpret_cast<float2*>(out + (size_t)i * NCH);
                #pragma unroll
                for (int c = 0; c < 9; c++)
                    o2[c] = make_float2(t[2 * c], t[2 * c + 1]);
            }
        }
        #pragma unroll
        for (int o = 16; o > 0; o >>= 1)
            #pragma unroll
            for (int c = 0; c < 18; c++)
                acc[c] += __shfl_xor_sync(FULL, acc[c], o);
        #pragma unroll
        for (int c = 0; c < 18; c++) acc[c] *= zi2;
        // rotation normalize (channels 10..13)
        float nr = sqrtf(acc[10] * acc[10] + acc[11] * acc[11] +
                         acc[12] * acc[12] + acc[13] * acc[13]);
        float ri = 1.f / fmaxf(nr, 1e-12f);
        acc[10] *= ri; acc[11] *= ri; acc[12] *= ri; acc[13] *= ri;
        acc[17] = m2;   // mkeep = segment max keep over active
        #pragma unroll
        for (int q = 0; q < MAXE; q++) {
            if (!((amask >> q) & 1u)) continue;
            int i = idxv[q];
            float sf = (i == rep) ? 1.0f : DKS;
            float2* o2 = reinterpret_cast<float2*>(out + (size_t)i * NCH);
            o2[0] = make_float2(acc[0], acc[1]);
            o2[1] = make_float2(acc[2], acc[3]);
            o2[2] = make_float2(acc[4], acc[5]);
            o2[3] = make_float2(acc[6] * sf, acc[7]);
            o2[4] = make_float2(acc[8], acc[9]);
            o2[5] = make_float2(acc[10], acc[11]);
            o2[6] = make_float2(acc[12], acc[13]);
            o2[7] = make_float2(acc[14], acc[15]);
            o2[8] = make_float2(acc[16], acc[17] * sf);
        }
    }

    // ============ chunks B0/B1: instance_affinity 18..49 ============
    #pragma unroll
    for (int h = 0; h < 2; h++) {
        float acc[16];
        #pragma unroll
        for (int c = 0; c < 16; c++) acc[c] = 0.f;
        #pragma unroll
        for (int q = 0; q < MAXE; q++) {
            int p = lane + q * 32;
            if (p >= n) continue;
            int i = idxv[q];
            float t[16];
            const float4* ip = reinterpret_cast<const float4*>(ins) +
                               (size_t)i * 8 + h * 4;
            #pragma unroll
            for (int v4i = 0; v4i < 4; v4i++) {
                float4 v = ip[v4i];
                t[4 * v4i + 0] = v.x; t[4 * v4i + 1] = v.y;
                t[4 * v4i + 2] = v.z; t[4 * v4i + 3] = v.w;
            }
            if ((amask >> q) & 1u) {
                float w = __expf(kpv[q]);
                #pragma unroll
                for (int c = 0; c < 16; c++) acc[c] += w * t[c];
            } else {
                float2* o2 = reinterpret_cast<float2*>(
                    out + (size_t)i * NCH + 18 + 16 * h);
                #pragma unroll
                for (int c = 0; c < 8; c++)
                    o2[c] = make_float2(t[2 * c], t[2 * c + 1]);
            }
        }
        #pragma unroll
        for (int o = 16; o > 0; o >>= 1)
            #pragma unroll
            for (int c = 0; c < 16; c++)
                acc[c] += __shfl_xor_sync(FULL, acc[c], o);
        #pragma unroll
        for (int c = 0; c < 16; c++) acc[c] *= zi2;
        #pragma unroll
        for (int q = 0; q < MAXE; q++) {
            if (!((amask >> q) & 1u)) continue;
            int i = idxv[q];
            float2* o2 = reinterpret_cast<float2*>(
                out + (size_t)i * NCH + 18 + 16 * h);
            #pragma unroll
            for (int c = 0; c < 8; c++)
                o2[c] = make_float2(acc[2 * c], acc[2 * c + 1]);
        }
    }

    // ============ chunk C: motion_code 50..65 ============
    {
        float acc[16];
        #pragma unroll
        for (int c = 0; c < 16; c++) acc[c] = 0.f;
        #pragma unroll
        for (int q = 0; q < MAXE; q++) {
            int p = lane + q * 32;
            if (p >= n) continue;
            int i = idxv[q];
            float t[16];
            const float4* mp = reinterpret_cast<const float4*>(mot) +
                               (size_t)i * 4;
            #pragma unroll
            for (int v4i = 0; v4i < 4; v4i++) {
                float4 v = mp[v4i];
                t[4 * v4i + 0] = v.x; t[4 * v4i + 1] = v.y;
                t[4 * v4i + 2] = v.z; t[4 * v4i + 3] = v.w;
            }
            if ((amask >> q) & 1u) {
                float w = __expf(kpv[q]);
                #pragma unroll
                for (int c = 0; c < 16; c++) acc[c] += w * t[c];
            } else {
                float2* o2 = reinterpret_cast<float2*>(
                    out + (size_t)i * NCH + 50);
                #pragma unroll
                for (int c = 0; c < 8; c++)
                    o2[c] = make_float2(t[2 * c], t[2 * c + 1]);
            }
        }
        #pragma unroll
        for (int o = 16; o > 0; o >>= 1)
            #pragma unroll
            for (int c = 0; c < 16; c++)
                acc[c] += __shfl_xor_sync(FULL, acc[c], o);
        #pragma unroll
        for (int c = 0; c < 16; c++) acc[c] *= zi2;
        #pragma unroll
        for (int q = 0; q < MAXE; q++) {
            if (!((amask >> q) & 1u)) continue;
            int i = idxv[q];
            float2* o2 = reinterpret_cast<float2*>(
                out + (size_t)i * NCH + 50);
            #pragma unroll
            for (int c = 0; c < 8; c++)
                o2[c] = make_float2(acc[2 * c], acc[2 * c + 1]);
        }
    }
}

// ---------------- launcher ----------------
extern "C" void kernel_launch(void* const* d_in, const int* in_sizes, int n_in,
                              void* d_out, int out_size) {
    const float* cen = (const float*)d_in[0];
    const float* off = (const float*)d_in[1];
    const float* opa = (const float*)d_in[2];
    const float* sca = (const float*)d_in[3];
    const float* rot = (const float*)d_in[4];
    const float* fdc = (const float*)d_in[5];
    const float* kp  = (const float*)d_in[6];
    const float* ins = (const float*)d_in[7];
    const float* mot = (const float*)d_in[8];
    const int*   gid = (const int*)d_in[9];
    float* out = (float*)d_out;

    const int TB = 256;
    k_init  <<<(NSEG + TB - 1) / TB, TB>>>();
    k_bucket<<<(BN + TB - 1) / TB, TB>>>(cen, off, opa, sca, rot, fdc,
                                         kp, ins, mot, gid, out);
    k_mega  <<<(NSEG * 32 + TB - 1) / TB, TB>>>(cen, off, opa, sca, rot, fdc,
                                                kp, ins, mot, out);
}

// round 5
// speedup vs baseline: 1.9680x; 1.9680x over previous
#include <cuda_runtime.h>
#include <math.h>

#define BN    737280      // total elements (8 * 92160)
#define NPIX  92160       // elements per (b,t) slice
#define NTRK  512
#define NSEG  4096        // 8 * 512
#define NCH   66
#define WCH   68          // padded accumulator row (16B-aligned stride)
#define REPL  4           // accumulator replicas (contention spreading)
#define THR   2.0f
#define DKS   0.05f

// ---------------- scratch (device globals; no allocation) ----------------
__device__ int                        g_cnt[REPL * NSEG];
__device__ __align__(16) float4       g_p1[REPL * NSEG];          // {z1, wx, wy, wz}
__device__ unsigned long long         g_repkey[REPL * NSEG];      // (~fok(k0))<<32 | idx
__device__ __align__(16) float        g_wsum[REPL * NSEG * WCH];  // [0..65]=w*ch, [66]=z2
__device__ __align__(16) float        g_srow[NSEG * WCH];         // finalized segment row
__device__ int                        g_rep[NSEG];
__device__ unsigned char              g_flags[BN];

// ordered-uint mapping for floats (bijective, order-preserving)
__device__ __forceinline__ unsigned fok(float f) {
    unsigned b = __float_as_uint(f);
    return (b & 0x80000000u) ? ~b : (b | 0x80000000u);
}
__device__ __forceinline__ float kof(unsigned u) {
    unsigned b = (u & 0x80000000u) ? (u & 0x7FFFFFFFu) : ~u;
    return __uint_as_float(b);
}
__device__ __forceinline__ int seg_of(int i, int g) {
    return (i / NPIX) * NTRK + g;
}
__device__ __forceinline__ void red_add_v4(float* p, float a, float b, float c, float d) {
    asm volatile("red.global.add.v4.f32 [%0], {%1, %2, %3, %4};"
                 :: "l"(p), "f"(a), "f"(b), "f"(c), "f"(d) : "memory");
}

// load all 66 channels for element i into buf
// order: center(0-2) offset(3-5) opacity(6) scale(7-9) rotation(10-13)
//        feat_dc(14-16) keep(17) inst(18-49) motion(50-65)
__device__ __forceinline__ void load_row(
    int i, float* buf,
    const float* __restrict__ cen, const float* __restrict__ off,
    const float* __restrict__ opa, const float* __restrict__ sca,
    const float* __restrict__ rot, const float* __restrict__ fdc,
    const float* __restrict__ kp,  const float* __restrict__ ins,
    const float* __restrict__ mot) {
    #pragma unroll
    for (int c = 0; c < 3; c++) buf[c]      = cen[3 * i + c];
    #pragma unroll
    for (int c = 0; c < 3; c++) buf[3 + c]  = off[3 * i + c];
    buf[6] = opa[i];
    #pragma unroll
    for (int c = 0; c < 3; c++) buf[7 + c]  = sca[3 * i + c];
    {
        float4 r4 = reinterpret_cast<const float4*>(rot)[i];
        buf[10] = r4.x; buf[11] = r4.y; buf[12] = r4.z; buf[13] = r4.w;
    }
    #pragma unroll
    for (int c = 0; c < 3; c++) buf[14 + c] = fdc[3 * i + c];
    buf[17] = kp[i];
    const float4* ip = reinterpret_cast<const float4*>(ins) + (size_t)i * 8;
    #pragma unroll
    for (int q = 0; q < 8; q++) {
        float4 v = ip[q];
        buf[18 + 4 * q + 0] = v.x; buf[18 + 4 * q + 1] = v.y;
        buf[18 + 4 * q + 2] = v.z; buf[18 + 4 * q + 3] = v.w;
    }
    const float4* mp = reinterpret_cast<const float4*>(mot) + (size_t)i * 4;
    #pragma unroll
    for (int q = 0; q < 4; q++) {
        float4 v = mp[q];
        buf[50 + 4 * q + 0] = v.x; buf[50 + 4 * q + 1] = v.y;
        buf[50 + 4 * q + 2] = v.z; buf[50 + 4 * q + 3] = v.w;
    }
}

// ---------------- kernels ----------------
__global__ void k_init() {
    int i = blockIdx.x * blockDim.x + threadIdx.x;
    if (i < REPL * NSEG * WCH) g_wsum[i] = 0.0f;
    if (i < REPL * NSEG) {
        g_cnt[i]    = 0;
        g_p1[i]     = make_float4(0.f, 0.f, 0.f, 0.f);
        g_repkey[i] = 0xFFFFFFFFFFFFFFFFull;
    }
}

// count + phase-1 softmax sums into per-replica accumulators
__global__ void k1(const float* __restrict__ cen, const float* __restrict__ kp,
                   const int* __restrict__ gid) {
    int i = blockIdx.x * blockDim.x + threadIdx.x;
    if (i >= BN) return;
    int g = gid[i];
    if (g < 0) return;
    int s = seg_of(i, g) + (blockIdx.x & (REPL - 1)) * NSEG;
    atomicAdd(&g_cnt[s], 1);
    float e = __expf(kp[i]);
    red_add_v4(&g_p1[s].x, e, e * cen[3 * i + 0], e * cen[3 * i + 1], e * cen[3 * i + 2]);
}

// collapse phase-1 replicas into replica 0
__global__ void k_p1red() {
    int s = blockIdx.x * blockDim.x + threadIdx.x;
    if (s >= NSEG) return;
    int cnt = 0;
    float4 acc = make_float4(0.f, 0.f, 0.f, 0.f);
    #pragma unroll
    for (int r = 0; r < REPL; r++) {
        cnt += g_cnt[r * NSEG + s];
        float4 p = g_p1[r * NSEG + s];
        acc.x += p.x; acc.y += p.y; acc.z += p.z; acc.w += p.w;
    }
    g_cnt[s] = cnt;
    g_p1[s]  = acc;
}

// activity + weighted accumulation (per-replica) + representative key
__global__ void __launch_bounds__(256)
k2(const float* __restrict__ cen, const float* __restrict__ off,
   const float* __restrict__ opa, const float* __restrict__ sca,
   const float* __restrict__ rot, const float* __restrict__ fdc,
   const float* __restrict__ kp,  const float* __restrict__ ins,
   const float* __restrict__ mot, const int* __restrict__ gid) {
    int i = blockIdx.x * blockDim.x + threadIdx.x;
    if (i >= BN) return;
    int g = gid[i];
    int s = 0;
    unsigned char f = 0;
    float k0 = 0.0f;
    if (g >= 0) {
        s = seg_of(i, g);
        if (g_cnt[s] >= 2) {
            float4 p = g_p1[s];
            float zinv = 1.0f / fmaxf(p.x, 1e-20f);
            float dx = cen[3 * i + 0] - p.y * zinv;
            float dy = cen[3 * i + 1] - p.z * zinv;
            float dz = cen[3 * i + 2] - p.w * zinv;
            if (sqrtf(dx * dx + dy * dy + dz * dz) <= THR) {
                f = 1;
                k0 = kp[i];
            }
        }
    }
    g_flags[i] = f;
    if (!f) return;

    float buf[NCH];
    load_row(i, buf, cen, off, opa, sca, rot, fdc, kp, ins, mot);
    float e = __expf(k0);
    int sr = s + (blockIdx.x & (REPL - 1)) * NSEG;
    float* ws = &g_wsum[(size_t)sr * WCH];
    #pragma unroll
    for (int q = 0; q < 16; q++)
        red_add_v4(ws + 4 * q,
                   e * buf[4 * q + 0], e * buf[4 * q + 1],
                   e * buf[4 * q + 2], e * buf[4 * q + 3]);
    red_add_v4(ws + 64, e * buf[64], e * buf[65], e, 0.0f);

    unsigned long long key =
        ((unsigned long long)(~fok(k0)) << 32) | (unsigned)i;
    atomicMin(&g_repkey[sr], key);
}

// finalize one output row per segment (sum replicas, means, rot norm, mkeep, rep)
__global__ void k_seg() {
    int s = blockIdx.x * blockDim.x + threadIdx.x;
    if (s >= NSEG) return;
    float row[WCH];
    #pragma unroll
    for (int c = 0; c < WCH; c++) row[c] = 0.f;
    unsigned long long key = 0xFFFFFFFFFFFFFFFFull;
    #pragma unroll
    for (int r = 0; r < REPL; r++) {
        const float* ws = &g_wsum[(size_t)(r * NSEG + s) * WCH];
        #pragma unroll
        for (int c = 0; c < WCH - 1; c++) row[c] += ws[c];
        unsigned long long k = g_repkey[r * NSEG + s];
        if (k < key) key = k;
    }
    float zinv = 1.0f / fmaxf(row[66], 1e-20f);
    #pragma unroll
    for (int c = 0; c < NCH; c++) row[c] *= zinv;
    float nr = sqrtf(row[10] * row[10] + row[11] * row[11] +
                     row[12] * row[12] + row[13] * row[13]);
    float rinv = 1.0f / fmaxf(nr, 1e-12f);
    row[10] *= rinv; row[11] *= rinv; row[12] *= rinv; row[13] *= rinv;

    g_rep[s] = (int)(unsigned)(key & 0xFFFFFFFFull);
    row[17] = kof(~(unsigned)(key >> 32));  // m2 = segment max keep
    float* r = &g_srow[(size_t)s * WCH];
    #pragma unroll
    for (int c = 0; c < NCH; c++) r[c] = row[c];
}

// output: gather (segment row for active, raw channels for inactive),
// stage in smem, write fully coalesced
__global__ void __launch_bounds__(128)
k3(const float* __restrict__ cen, const float* __restrict__ off,
   const float* __restrict__ opa, const float* __restrict__ sca,
   const float* __restrict__ rot, const float* __restrict__ fdc,
   const float* __restrict__ kp,  const float* __restrict__ ins,
   const float* __restrict__ mot, const int* __restrict__ gid,
   float* __restrict__ out) {
    __shared__ float stage[128 * NCH];   // 33,792 B
    int tid = threadIdx.x;
    int i = blockIdx.x * 128 + tid;

    float buf[NCH];
    if (g_flags[i]) {
        int s = seg_of(i, gid[i]);
        const float* r = &g_srow[(size_t)s * WCH];
        #pragma unroll
        for (int c = 0; c < NCH; c++) buf[c] = r[c];
        float sfac = (i == g_rep[s]) ? 1.0f : DKS;
        buf[6]  *= sfac;
        buf[17] *= sfac;
    } else {
        load_row(i, buf, cen, off, opa, sca, rot, fdc, kp, ins, mot);
    }
    #pragma unroll
    for (int c = 0; c < NCH; c++) stage[tid * NCH + c] = buf[c];
    __syncthreads();

    float4* dst = reinterpret_cast<float4*>(out + (size_t)blockIdx.x * 128 * NCH);
    const float4* src = reinterpret_cast<const float4*>(stage);
    for (int idx = tid; idx < (128 * NCH) / 4; idx += 128)
        dst[idx] = src[idx];
}

// ---------------- launcher ----------------
extern "C" void kernel_launch(void* const* d_in, const int* in_sizes, int n_in,
                              void* d_out, int out_size) {
    const float* cen = (const float*)d_in[0];
    const float* off = (const float*)d_in[1];
    const float* opa = (const float*)d_in[2];
    const float* sca = (const float*)d_in[3];
    const float* rot = (const float*)d_in[4];
    const float* fdc = (const float*)d_in[5];
    const float* kp  = (const float*)d_in[6];
    const float* ins = (const float*)d_in[7];
    const float* mot = (const float*)d_in[8];
    const int*   gid = (const int*)d_in[9];
    float* out = (float*)d_out;

    const int TB = 256;
    const int GB = (BN + TB - 1) / TB;                    // 2880
    const int GI = (REPL * NSEG * WCH + TB - 1) / TB;     // 4352

    k_init <<<GI, TB>>>();
    k1     <<<GB, TB>>>(cen, kp, gid);
    k_p1red<<<NSEG / TB, TB>>>();
    k2     <<<GB, TB>>>(cen, off, opa, sca, rot, fdc, kp, ins, mot, gid);
    k_seg  <<<NSEG / TB, TB>>>();
    k3     <<<BN / 128, 128>>>(cen, off, opa, sca, rot, fdc, kp, ins, mot, gid, out);
}